// round 1
// baseline (speedup 1.0000x reference)
#include <cuda_runtime.h>
#include <cstdint>

#define N_NODES 50000
#define N_EDGES 800000
#define D 256

// ---------------- device scratch (no runtime allocation allowed) ----------------
__device__ int   g_is64;
__device__ int   g_deg[N_NODES];
__device__ int   g_cursor[N_NODES];
__device__ int   g_rowstart[N_NODES + 1];
__device__ int   g_nbr[N_EDGES];
__device__ float g_agg[(size_t)N_NODES * D];
__device__ float g_h1[(size_t)N_NODES * D];
__device__ float g_h2[(size_t)N_NODES * D];

// ---------------- edge dtype detection ----------------
// If edge_index is int32, interpreting the buffer as int64 combines pairs
// (a | b<<32) which is >= 2^32 unless b==0 (prob ~1/50000 per element).
__global__ void k_detect(const void* edge) {
    const long long* e = (const long long*)edge;
    int ok = 1;
    for (int i = 0; i < 16; i++) {
        long long v = e[i];
        if (v < 0 || v >= (long long)N_NODES) ok = 0;
    }
    g_is64 = ok;
}

__device__ __forceinline__ int edge_at(const void* edge, int idx) {
    if (g_is64) return (int)((const long long*)edge)[idx];
    return ((const int*)edge)[idx];
}

// ---------------- CSR build ----------------
__global__ void k_init() {
    int i = blockIdx.x * blockDim.x + threadIdx.x;
    if (i < N_NODES) { g_deg[i] = 0; g_cursor[i] = 0; }
}

__global__ void k_count(const void* __restrict__ edge) {
    int e = blockIdx.x * blockDim.x + threadIdx.x;
    if (e >= N_EDGES) return;
    int dst = edge_at(edge, N_EDGES + e);
    atomicAdd(&g_deg[dst], 1);
}

// single-block inclusive scan over degrees -> rowstart
__global__ void k_scan() {
    __shared__ int warpsum[32];
    __shared__ int carry;
    int tid = threadIdx.x, lane = tid & 31, w = tid >> 5;
    if (tid == 0) { carry = 0; g_rowstart[0] = 0; }
    __syncthreads();
    for (int base = 0; base < N_NODES; base += 1024) {
        int i = base + tid;
        int v = (i < N_NODES) ? g_deg[i] : 0;
        int sv = v;
        #pragma unroll
        for (int off = 1; off < 32; off <<= 1) {
            int t = __shfl_up_sync(0xffffffffu, sv, off);
            if (lane >= off) sv += t;
        }
        if (lane == 31) warpsum[w] = sv;
        __syncthreads();
        if (w == 0) {
            int s = warpsum[lane];
            #pragma unroll
            for (int off = 1; off < 32; off <<= 1) {
                int t = __shfl_up_sync(0xffffffffu, s, off);
                if (lane >= off) s += t;
            }
            warpsum[lane] = s;
        }
        __syncthreads();
        int add = carry + ((w > 0) ? warpsum[w - 1] : 0);
        if (i < N_NODES) g_rowstart[i + 1] = add + sv;
        __syncthreads();
        if (tid == 0) carry += warpsum[31];
        __syncthreads();
    }
}

__global__ void k_fill(const void* __restrict__ edge) {
    int e = blockIdx.x * blockDim.x + threadIdx.x;
    if (e >= N_EDGES) return;
    int src = edge_at(edge, e);
    int dst = edge_at(edge, N_EDGES + e);
    int p = atomicAdd(&g_cursor[dst], 1);
    g_nbr[g_rowstart[dst] + p] = src;
}

// ---------------- mean aggregation: warp per node, pure gather ----------------
__global__ void k_aggregate(const float* __restrict__ X, float* __restrict__ out) {
    int gw = (blockIdx.x * blockDim.x + threadIdx.x) >> 5;
    int lane = threadIdx.x & 31;
    if (gw >= N_NODES) return;
    int s = g_rowstart[gw], e = g_rowstart[gw + 1];
    float4 a0 = make_float4(0.f, 0.f, 0.f, 0.f);
    float4 a1 = make_float4(0.f, 0.f, 0.f, 0.f);
    for (int j = s; j < e; j++) {
        int src = g_nbr[j];
        const float4* row = (const float4*)(X + (size_t)src * D);
        float4 v0 = __ldg(&row[lane]);
        float4 v1 = __ldg(&row[lane + 32]);
        a0.x += v0.x; a0.y += v0.y; a0.z += v0.z; a0.w += v0.w;
        a1.x += v1.x; a1.y += v1.y; a1.z += v1.z; a1.w += v1.w;
    }
    int cnt = e - s;
    float inv = 1.0f / (float)(cnt > 1 ? cnt : 1);
    a0.x *= inv; a0.y *= inv; a0.z *= inv; a0.w *= inv;
    a1.x *= inv; a1.y *= inv; a1.z *= inv; a1.w *= inv;
    float4* o = (float4*)(out + (size_t)gw * D);
    o[lane] = a0;
    o[lane + 32] = a1;
}

// ---------------- fused (dual) SGEMM: C = relu?(A1@W1^T [+ A2@W2^T] + bias) ----
// A: [M,256] row-major, W: [256,256] row-major (C[i,o] = sum_k A[i,k]*W[o,k])
// BM=128, BN=64, BK=16, 256 threads, 8x4 per-thread tile.
__global__ void __launch_bounds__(256) k_gemm(
    const float* __restrict__ A1, const float* __restrict__ W1,
    const float* __restrict__ A2, const float* __restrict__ W2,
    const float* __restrict__ bias, float* __restrict__ C,
    int M, int dual, int relu)
{
    const int BM = 128, BN = 64, BK = 16;
    __shared__ float As[BK][BM];
    __shared__ float Bs[BK][BN];
    int bm = blockIdx.x * BM;
    int bn = blockIdx.y * BN;
    int tid = threadIdx.x;
    int tx = tid & 15, ty = tid >> 4;

    float acc[8][4];
    #pragma unroll
    for (int m = 0; m < 8; m++)
        #pragma unroll
        for (int n = 0; n < 4; n++) acc[m][n] = 0.f;

    int nk = dual ? (512 / BK) : (256 / BK);
    for (int kt = 0; kt < nk; kt++) {
        int kk = kt * BK;
        const float* A = A1;
        const float* W = W1;
        if (kk >= 256) { A = A2; W = W2; kk -= 256; }

        // A tile: 128 rows x 16 k  (512 float4, 2 per thread), stored transposed
        #pragma unroll
        for (int i = 0; i < 2; i++) {
            int f = tid + i * 256;
            int r = f >> 2, c = f & 3;
            int grow = bm + r;
            float4 v = make_float4(0.f, 0.f, 0.f, 0.f);
            if (grow < M) v = *(const float4*)(A + (size_t)grow * 256 + kk + c * 4);
            As[c * 4 + 0][r] = v.x; As[c * 4 + 1][r] = v.y;
            As[c * 4 + 2][r] = v.z; As[c * 4 + 3][r] = v.w;
        }
        // W tile: 64 rows(n) x 16 k (256 float4, 1 per thread), stored [k][n]
        {
            int n = tid >> 2, c = tid & 3;
            float4 v = *(const float4*)(W + (size_t)(bn + n) * 256 + kk + c * 4);
            Bs[c * 4 + 0][n] = v.x; Bs[c * 4 + 1][n] = v.y;
            Bs[c * 4 + 2][n] = v.z; Bs[c * 4 + 3][n] = v.w;
        }
        __syncthreads();

        #pragma unroll
        for (int k = 0; k < BK; k++) {
            float4 a0 = *(const float4*)&As[k][ty * 8];
            float4 a1 = *(const float4*)&As[k][ty * 8 + 4];
            float4 b4 = *(const float4*)&Bs[k][tx * 4];
            float am[8] = {a0.x, a0.y, a0.z, a0.w, a1.x, a1.y, a1.z, a1.w};
            float bv[4] = {b4.x, b4.y, b4.z, b4.w};
            #pragma unroll
            for (int m = 0; m < 8; m++)
                #pragma unroll
                for (int n = 0; n < 4; n++)
                    acc[m][n] = fmaf(am[m], bv[n], acc[m][n]);
        }
        __syncthreads();
    }

    float4 bv = *(const float4*)(bias + bn + tx * 4);
    #pragma unroll
    for (int m = 0; m < 8; m++) {
        int row = bm + ty * 8 + m;
        if (row >= M) continue;
        float4 o;
        o.x = acc[m][0] + bv.x;
        o.y = acc[m][1] + bv.y;
        o.z = acc[m][2] + bv.z;
        o.w = acc[m][3] + bv.w;
        if (relu) {
            o.x = fmaxf(o.x, 0.f); o.y = fmaxf(o.y, 0.f);
            o.z = fmaxf(o.z, 0.f); o.w = fmaxf(o.w, 0.f);
        }
        *(float4*)(C + (size_t)row * 256 + bn + tx * 4) = o;
    }
}

// ---------------- decoder: logits (N=8) + softmax, warp per node -------------
__global__ void __launch_bounds__(128) k_decoder(
    const float* __restrict__ H, const float* __restrict__ Wm2,
    const float* __restrict__ bm2, float* __restrict__ out)
{
    __shared__ float sW[8 * 256];
    int tid = threadIdx.x;
    #pragma unroll
    for (int i = 0; i < 16; i++) sW[tid + i * 128] = Wm2[tid + i * 128];
    __syncthreads();

    int lane = tid & 31, w = tid >> 5;
    int node = blockIdx.x * 4 + w;
    if (node >= N_NODES) return;

    float acc[8] = {0.f, 0.f, 0.f, 0.f, 0.f, 0.f, 0.f, 0.f};
    #pragma unroll
    for (int j = 0; j < 8; j++) {
        float v = H[(size_t)node * 256 + j * 32 + lane];
        #pragma unroll
        for (int o = 0; o < 8; o++)
            acc[o] = fmaf(v, sW[o * 256 + j * 32 + lane], acc[o]);
    }
    #pragma unroll
    for (int o = 0; o < 8; o++)
        #pragma unroll
        for (int off = 16; off >= 1; off >>= 1)
            acc[o] += __shfl_xor_sync(0xffffffffu, acc[o], off);

    if (lane < 8) {
        float logit = acc[lane] + bm2[lane];
        float m = logit;
        #pragma unroll
        for (int off = 4; off >= 1; off >>= 1)
            m = fmaxf(m, __shfl_xor_sync(0xffu, m, off));
        float ex = expf(logit - m);
        float ssum = ex;
        #pragma unroll
        for (int off = 4; off >= 1; off >>= 1)
            ssum += __shfl_xor_sync(0xffu, ssum, off);
        out[(size_t)node * 8 + lane] = ex / ssum;
    }
}

// ---------------- launch ----------------
extern "C" void kernel_launch(void* const* d_in, const int* in_sizes, int n_in,
                              void* d_out, int out_size) {
    const float* x   = (const float*)d_in[0];
    const void*  edge = d_in[1];
    const float* W1l = (const float*)d_in[2];
    const float* b1  = (const float*)d_in[3];
    const float* W1r = (const float*)d_in[4];
    const float* W2l = (const float*)d_in[5];
    const float* b2  = (const float*)d_in[6];
    const float* W2r = (const float*)d_in[7];
    const float* Wm1 = (const float*)d_in[8];
    const float* bm1 = (const float*)d_in[9];
    const float* Wm2 = (const float*)d_in[10];
    const float* bm2 = (const float*)d_in[11];
    float* out = (float*)d_out;

    float *agg, *h1, *h2;
    cudaGetSymbolAddress((void**)&agg, g_agg);
    cudaGetSymbolAddress((void**)&h1, g_h1);
    cudaGetSymbolAddress((void**)&h2, g_h2);

    // CSR build (reused by both SAGE layers)
    k_detect<<<1, 1>>>(edge);
    k_init<<<(N_NODES + 255) / 256, 256>>>();
    k_count<<<(N_EDGES + 255) / 256, 256>>>(edge);
    k_scan<<<1, 1024>>>();
    k_fill<<<(N_EDGES + 255) / 256, 256>>>(edge);

    dim3 gg((N_NODES + 127) / 128, 4);
    int aggBlocks = (N_NODES * 32 + 255) / 256;

    // layer 1: h1 = relu(mean(x) @ W1l^T + x @ W1r^T + b1)
    k_aggregate<<<aggBlocks, 256>>>(x, agg);
    k_gemm<<<gg, 256>>>(agg, W1l, x, W1r, b1, h1, N_NODES, 1, 1);

    // layer 2: h2 = relu(mean(h1) @ W2l^T + h1 @ W2r^T + b2)
    k_aggregate<<<aggBlocks, 256>>>(h1, agg);
    k_gemm<<<gg, 256>>>(agg, W2l, h1, W2r, b2, h2, N_NODES, 1, 1);

    // MLP hidden: h1 = relu(h2 @ Wm1^T + bm1)   (reuse h1 buffer)
    k_gemm<<<gg, 256>>>(h2, Wm1, nullptr, nullptr, bm1, h1, N_NODES, 0, 1);

    // decoder + softmax
    k_decoder<<<(N_NODES + 3) / 4, 128>>>(h1, Wm2, bm2, out);
}

// round 4
// speedup vs baseline: 2.1466x; 2.1466x over previous
#include <cuda_runtime.h>
#include <cuda_bf16.h>
#include <cstdint>

#define N_NODES 50000
#define N_EDGES 800000
#define DF 256

// ---------------- device scratch ----------------
__device__ int   g_is64;
__device__ int   g_deg[N_NODES];
__device__ int   g_cursor[N_NODES];
__device__ int   g_rowstart[N_NODES + 1];
__device__ int   g_blocksum[64];
__device__ int   g_blockoff[64];
__device__ int   g_nbr[N_EDGES];
__device__ float g_agg[(size_t)N_NODES * DF];
__device__ float g_h1[(size_t)N_NODES * DF];
__device__ float g_h2[(size_t)N_NODES * DF];

// ---------------- edge dtype detection ----------------
__global__ void k_detect(const void* edge) {
    const long long* e = (const long long*)edge;
    int ok = 1;
    for (int i = 0; i < 16; i++) {
        long long v = e[i];
        if (v < 0 || v >= (long long)N_NODES) ok = 0;
    }
    g_is64 = ok;
}

__device__ __forceinline__ int edge_at(const void* edge, int idx) {
    if (g_is64) return (int)((const long long*)edge)[idx];
    return ((const int*)edge)[idx];
}

// ---------------- CSR build ----------------
__global__ void k_init() {
    int i = blockIdx.x * blockDim.x + threadIdx.x;
    if (i < N_NODES) { g_deg[i] = 0; g_cursor[i] = 0; }
}

__global__ void k_count(const void* __restrict__ edge) {
    int e = blockIdx.x * blockDim.x + threadIdx.x;
    if (e >= N_EDGES) return;
    int dst = edge_at(edge, N_EDGES + e);
    atomicAdd(&g_deg[dst], 1);
}

__global__ void k_scanA() {
    __shared__ int ws[32];
    int b = blockIdx.x, t = threadIdx.x, lane = t & 31, w = t >> 5;
    int i = b * 1024 + t;
    int v = (i < N_NODES) ? g_deg[i] : 0;
    int sv = v;
    #pragma unroll
    for (int off = 1; off < 32; off <<= 1) {
        int x = __shfl_up_sync(0xffffffffu, sv, off);
        if (lane >= off) sv += x;
    }
    if (lane == 31) ws[w] = sv;
    __syncthreads();
    if (w == 0) {
        int s = ws[lane];
        #pragma unroll
        for (int off = 1; off < 32; off <<= 1) {
            int x = __shfl_up_sync(0xffffffffu, s, off);
            if (lane >= off) s += x;
        }
        ws[lane] = s;
    }
    __syncthreads();
    int tot = sv + ((w > 0) ? ws[w - 1] : 0);
    if (i < N_NODES) g_rowstart[i + 1] = tot;
    if (t == 1023) g_blocksum[b] = tot;
    if (b == 0 && t == 0) g_rowstart[0] = 0;
}

__global__ void k_scanB() {
    __shared__ int s[64];
    int t = threadIdx.x;
    s[t] = (t < 49) ? g_blocksum[t] : 0;
    __syncthreads();
    if (t == 0) {
        int acc = 0;
        for (int j = 0; j < 49; j++) { int x = s[j]; s[j] = acc; acc += x; }
    }
    __syncthreads();
    if (t < 49) g_blockoff[t] = s[t];
}

__global__ void k_scanC() {
    int b = blockIdx.x, t = threadIdx.x;
    int i = b * 1024 + t;
    if (i < N_NODES) g_rowstart[i + 1] += g_blockoff[b];
}

__global__ void k_fill(const void* __restrict__ edge) {
    int e = blockIdx.x * blockDim.x + threadIdx.x;
    if (e >= N_EDGES) return;
    int src = edge_at(edge, e);
    int dst = edge_at(edge, N_EDGES + e);
    int p = atomicAdd(&g_cursor[dst], 1);
    g_nbr[g_rowstart[dst] + p] = src;
}

// ---------------- mean aggregation: warp per node ----------------
__global__ void k_aggregate(const float* __restrict__ X, float* __restrict__ out) {
    int gw = (blockIdx.x * blockDim.x + threadIdx.x) >> 5;
    int lane = threadIdx.x & 31;
    if (gw >= N_NODES) return;
    int s = g_rowstart[gw], e = g_rowstart[gw + 1];
    float4 a0 = make_float4(0.f, 0.f, 0.f, 0.f);
    float4 a1 = make_float4(0.f, 0.f, 0.f, 0.f);
    for (int j = s; j < e; j++) {
        int src = g_nbr[j];
        const float4* row = (const float4*)(X + (size_t)src * DF);
        float4 v0 = __ldg(&row[lane]);
        float4 v1 = __ldg(&row[lane + 32]);
        a0.x += v0.x; a0.y += v0.y; a0.z += v0.z; a0.w += v0.w;
        a1.x += v1.x; a1.y += v1.y; a1.z += v1.z; a1.w += v1.w;
    }
    int cnt = e - s;
    float inv = 1.0f / (float)(cnt > 1 ? cnt : 1);
    a0.x *= inv; a0.y *= inv; a0.z *= inv; a0.w *= inv;
    a1.x *= inv; a1.y *= inv; a1.z *= inv; a1.w *= inv;
    float4* o = (float4*)(out + (size_t)gw * DF);
    o[lane] = a0;
    o[lane + 32] = a1;
}

// ======================= mma.sync bf16 (3-term split) GEMM =======================
// C[M,256] = relu?( A1[M,256] @ W1^T  [+ A2 @ W2^T]  + bias )
// A = Ah + Al, B = Bh + Bl (bf16);  acc += Ah*Bh + Ah*Bl + Al*Bh  (fp32 acc).
// CTA tile: 128(M) x 64(N), K chunk = 32 floats. 8 warps: 4(M) x 2(N), warp tile 32x32.
// Both A and B smem tiles are [row][k] with k contiguous -> non-trans ldmatrix for both.

#define S_AH 0
#define S_AL 10240
#define S_BH 20480
#define S_BL 25600
#define S_BUF 30720
#define SMEM_GEMM (2 * S_BUF)

__device__ __forceinline__ uint32_t s2u(const void* p) {
    uint32_t a;
    asm("{ .reg .u64 t; cvta.to.shared.u64 t, %1; cvt.u32.u64 %0, t; }" : "=r"(a) : "l"(p));
    return a;
}

__device__ __forceinline__ uint32_t pack_bf16(float a, float b) {
    __nv_bfloat162 h = __floats2bfloat162_rn(a, b);
    return *reinterpret_cast<uint32_t*>(&h);
}

__device__ __forceinline__ void ldsm_x4(uint32_t* r, uint32_t addr) {
    asm volatile("ldmatrix.sync.aligned.m8n8.x4.shared.b16 {%0,%1,%2,%3}, [%4];"
                 : "=r"(r[0]), "=r"(r[1]), "=r"(r[2]), "=r"(r[3]) : "r"(addr));
}
__device__ __forceinline__ void mma16816(float* d, const uint32_t* a, uint32_t b0, uint32_t b1) {
    asm volatile(
        "mma.sync.aligned.m16n8k16.row.col.f32.bf16.bf16.f32 "
        "{%0,%1,%2,%3}, {%4,%5,%6,%7}, {%8,%9}, {%0,%1,%2,%3};"
        : "+f"(d[0]), "+f"(d[1]), "+f"(d[2]), "+f"(d[3])
        : "r"(a[0]), "r"(a[1]), "r"(a[2]), "r"(a[3]), "r"(b0), "r"(b1));
}

__global__ void __launch_bounds__(256, 2) k_gemm_mma(
    const float* __restrict__ A1, const float* __restrict__ W1,
    const float* __restrict__ A2, const float* __restrict__ W2,
    const float* __restrict__ bias, float* __restrict__ C,
    int M, int dual, int relu)
{
    extern __shared__ __align__(16) char smem[];
    uint32_t sb = s2u(smem);
    int tid = threadIdx.x, lane = tid & 31, wid = tid >> 5;
    int bm = blockIdx.x * 128, bn = blockIdx.y * 64;
    int wm = wid & 3, wn = wid >> 2;

    float acc[2][4][4];
    #pragma unroll
    for (int mt = 0; mt < 2; mt++)
        #pragma unroll
        for (int nt = 0; nt < 4; nt++)
            #pragma unroll
            for (int j = 0; j < 4; j++) acc[mt][nt][j] = 0.f;

    int nc = dual ? 16 : 8;
    float4 av[4], bv[2];

    // ---- global load of chunk c into registers ----
    auto gload = [&](int c) {
        const float* A = (c >= 8) ? A2 : A1;
        const float* W = (c >= 8) ? W2 : W1;
        int kk = (c & 7) * 32;
        #pragma unroll
        for (int i = 0; i < 4; i++) {
            int f = tid + i * 256, row = f >> 3, cc = f & 7;
            int grow = bm + row;
            av[i] = (grow < M) ? __ldg((const float4*)(A + (size_t)grow * 256 + kk + cc * 4))
                               : make_float4(0.f, 0.f, 0.f, 0.f);
        }
        #pragma unroll
        for (int i = 0; i < 2; i++) {
            int f = tid + i * 256, n = f >> 3, cc = f & 7;
            bv[i] = __ldg((const float4*)(W + (size_t)(bn + n) * 256 + kk + cc * 4));
        }
    };

    // ---- split to bf16 hi/lo and store into smem buffer ----
    auto sstore = [&](int buf) {
        char* st = smem + buf * S_BUF;
        #pragma unroll
        for (int i = 0; i < 4; i++) {
            int f = tid + i * 256, row = f >> 3, cc = f & 7;
            float4 v = av[i];
            float hx = __bfloat162float(__float2bfloat16_rn(v.x));
            float hy = __bfloat162float(__float2bfloat16_rn(v.y));
            float hz = __bfloat162float(__float2bfloat16_rn(v.z));
            float hw = __bfloat162float(__float2bfloat16_rn(v.w));
            uint2 hi = make_uint2(pack_bf16(hx, hy), pack_bf16(hz, hw));
            uint2 lo = make_uint2(pack_bf16(v.x - hx, v.y - hy), pack_bf16(v.z - hz, v.w - hw));
            *(uint2*)(st + S_AH + row * 80 + cc * 8) = hi;
            *(uint2*)(st + S_AL + row * 80 + cc * 8) = lo;
        }
        #pragma unroll
        for (int i = 0; i < 2; i++) {
            int f = tid + i * 256, n = f >> 3, cc = f & 7;
            float4 v = bv[i];
            float hx = __bfloat162float(__float2bfloat16_rn(v.x));
            float hy = __bfloat162float(__float2bfloat16_rn(v.y));
            float hz = __bfloat162float(__float2bfloat16_rn(v.z));
            float hw = __bfloat162float(__float2bfloat16_rn(v.w));
            uint2 hi = make_uint2(pack_bf16(hx, hy), pack_bf16(hz, hw));
            uint2 lo = make_uint2(pack_bf16(v.x - hx, v.y - hy), pack_bf16(v.z - hz, v.w - hw));
            *(uint2*)(st + S_BH + n * 80 + cc * 8) = hi;
            *(uint2*)(st + S_BL + n * 80 + cc * 8) = lo;
        }
    };

    gload(0);
    sstore(0);
    __syncthreads();

    for (int c = 0; c < nc; c++) {
        int buf = c & 1;
        if (c + 1 < nc) gload(c + 1);

        uint32_t base = sb + buf * S_BUF;
        // lane address patterns (non-trans ldmatrix for both A and B)
        int a_row = wm * 32 + (lane & 15);
        int a_col = ((lane >> 4) << 3);
        int b_row0 = wn * 32 + (lane & 7) + ((lane >> 4) << 3);
        int b_col = (((lane >> 3) & 1) << 3);

        #pragma unroll
        for (int ks = 0; ks < 2; ks++) {
            int kh = ks * 16;
            uint32_t ah[8], al[8], bh[8], bl[8];
            #pragma unroll
            for (int mt = 0; mt < 2; mt++) {
                uint32_t ad = base + S_AH + (a_row + mt * 16) * 80 + (kh + a_col) * 2;
                ldsm_x4(ah + mt * 4, ad);
                ldsm_x4(al + mt * 4, ad + (S_AL - S_AH));
            }
            #pragma unroll
            for (int h = 0; h < 2; h++) {
                uint32_t bd = base + S_BH + (b_row0 + h * 16) * 80 + (kh + b_col) * 2;
                ldsm_x4(bh + h * 4, bd);
                ldsm_x4(bl + h * 4, bd + (S_BL - S_BH));
            }
            #pragma unroll
            for (int mt = 0; mt < 2; mt++)
                #pragma unroll
                for (int nt = 0; nt < 4; nt++) {
                    mma16816(acc[mt][nt], ah + mt * 4, bh[nt * 2], bh[nt * 2 + 1]);
                    mma16816(acc[mt][nt], ah + mt * 4, bl[nt * 2], bl[nt * 2 + 1]);
                    mma16816(acc[mt][nt], al + mt * 4, bh[nt * 2], bh[nt * 2 + 1]);
                }
        }
        if (c + 1 < nc) sstore((c + 1) & 1);
        __syncthreads();
    }

    // ---- epilogue: bias + relu, write C ----
    int g = lane >> 2, tg = lane & 3;
    #pragma unroll
    for (int mt = 0; mt < 2; mt++) {
        int r0 = bm + wm * 32 + mt * 16 + g;
        #pragma unroll
        for (int nt = 0; nt < 4; nt++) {
            int col = bn + wn * 32 + nt * 8 + tg * 2;
            float bx = __ldg(bias + col), by = __ldg(bias + col + 1);
            float2 v0, v1;
            v0.x = acc[mt][nt][0] + bx; v0.y = acc[mt][nt][1] + by;
            v1.x = acc[mt][nt][2] + bx; v1.y = acc[mt][nt][3] + by;
            if (relu) {
                v0.x = fmaxf(v0.x, 0.f); v0.y = fmaxf(v0.y, 0.f);
                v1.x = fmaxf(v1.x, 0.f); v1.y = fmaxf(v1.y, 0.f);
            }
            if (r0 < M)     *(float2*)(C + (size_t)r0 * 256 + col) = v0;
            if (r0 + 8 < M) *(float2*)(C + (size_t)(r0 + 8) * 256 + col) = v1;
        }
    }
}

// ---------------- decoder: logits (8) + softmax, warp per node -------------
__global__ void __launch_bounds__(128) k_decoder(
    const float* __restrict__ H, const float* __restrict__ Wm2,
    const float* __restrict__ bm2, float* __restrict__ out)
{
    __shared__ float sW[8 * 256];
    int tid = threadIdx.x;
    #pragma unroll
    for (int i = 0; i < 16; i++) sW[tid + i * 128] = Wm2[tid + i * 128];
    __syncthreads();

    int lane = tid & 31, w = tid >> 5;
    int node = blockIdx.x * 4 + w;
    if (node >= N_NODES) return;

    float acc[8] = {0.f, 0.f, 0.f, 0.f, 0.f, 0.f, 0.f, 0.f};
    #pragma unroll
    for (int j = 0; j < 8; j++) {
        float v = H[(size_t)node * 256 + j * 32 + lane];
        #pragma unroll
        for (int o = 0; o < 8; o++)
            acc[o] = fmaf(v, sW[o * 256 + j * 32 + lane], acc[o]);
    }
    #pragma unroll
    for (int o = 0; o < 8; o++)
        #pragma unroll
        for (int off = 16; off >= 1; off >>= 1)
            acc[o] += __shfl_xor_sync(0xffffffffu, acc[o], off);

    if (lane < 8) {
        float logit = acc[lane] + bm2[lane];
        float m = logit;
        #pragma unroll
        for (int off = 4; off >= 1; off >>= 1)
            m = fmaxf(m, __shfl_xor_sync(0xffu, m, off));
        float ex = expf(logit - m);
        float ssum = ex;
        #pragma unroll
        for (int off = 4; off >= 1; off >>= 1)
            ssum += __shfl_xor_sync(0xffu, ssum, off);
        out[(size_t)node * 8 + lane] = ex / ssum;
    }
}

// ---------------- launch ----------------
extern "C" void kernel_launch(void* const* d_in, const int* in_sizes, int n_in,
                              void* d_out, int out_size) {
    const float* x    = (const float*)d_in[0];
    const void*  edge = d_in[1];
    const float* W1l = (const float*)d_in[2];
    const float* b1  = (const float*)d_in[3];
    const float* W1r = (const float*)d_in[4];
    const float* W2l = (const float*)d_in[5];
    const float* b2  = (const float*)d_in[6];
    const float* W2r = (const float*)d_in[7];
    const float* Wm1 = (const float*)d_in[8];
    const float* bm1 = (const float*)d_in[9];
    const float* Wm2 = (const float*)d_in[10];
    const float* bm2 = (const float*)d_in[11];
    float* out = (float*)d_out;

    float *agg, *h1, *h2;
    cudaGetSymbolAddress((void**)&agg, g_agg);
    cudaGetSymbolAddress((void**)&h1, g_h1);
    cudaGetSymbolAddress((void**)&h2, g_h2);

    cudaFuncSetAttribute(k_gemm_mma, cudaFuncAttributeMaxDynamicSharedMemorySize, SMEM_GEMM);

    // CSR build
    k_detect<<<1, 1>>>(edge);
    k_init<<<(N_NODES + 255) / 256, 256>>>();
    k_count<<<(N_EDGES + 255) / 256, 256>>>(edge);
    k_scanA<<<49, 1024>>>();
    k_scanB<<<1, 64>>>();
    k_scanC<<<49, 1024>>>();
    k_fill<<<(N_EDGES + 255) / 256, 256>>>(edge);

    int aggBlocks = (N_NODES * 32 + 255) / 256;
    dim3 gg((N_NODES + 127) / 128, 4);

    // layer 1
    k_aggregate<<<aggBlocks, 256>>>(x, agg);
    k_gemm_mma<<<gg, 256, SMEM_GEMM>>>(agg, W1l, x, W1r, b1, h1, N_NODES, 1, 1);

    // layer 2
    k_aggregate<<<aggBlocks, 256>>>(h1, agg);
    k_gemm_mma<<<gg, 256, SMEM_GEMM>>>(agg, W2l, h1, W2r, b2, h2, N_NODES, 1, 1);

    // MLP hidden
    k_gemm_mma<<<gg, 256, SMEM_GEMM>>>(h2, Wm1, nullptr, nullptr, bm1, h1, N_NODES, 0, 1);

    // decoder + softmax
    k_decoder<<<(N_NODES + 3) / 4, 128>>>(h1, Wm2, bm2, out);
}